// round 16
// baseline (speedup 1.0000x reference)
#include <cuda_runtime.h>
#include <cuda_fp16.h>
#include <math.h>

#define NN 50000
#define NE 800000
#define DIM 128
#define NH 8
#define HD 16
#define NET 5
#define NPB 16   // nodes per block in qkv/kt kernel

// ---- scratch (device globals; no allocation allowed) ----
__device__ float  gQ[NN * DIM];
__device__ __half gKtH[NET * NN * DIM];  // K transformed, fp16 (64MB)
__device__ __half gVH[NN * DIM];         // V, fp16 (12.8MB)
__device__ float  gAgg[NN * DIM];
__device__ float  gHid[NN * DIM];
__device__ __half gF1[NN * 4 * DIM];     // FFN intermediate, fp16 (51MB)
__device__ int    gEid[NE];              // packed: (etype<<20) | src
__device__ int    gCnt[NN];
__device__ int    gCur[NN];
__device__ int    gRow[NN + 1];
__device__ int    gBlkSum[64];
__device__ int    gBlkOff[64];
__device__ int    gTypeIdx[NN];
__device__ int    gTypeCnt[3];
__device__ int    gTypeCur[3];
__device__ int    gTypeOff[3];

// ---------------------------------------------------------------------------
// init + node-type histogram fused (one launch)
// ---------------------------------------------------------------------------
__global__ void init_hist_kernel(const int* __restrict__ ntype, int N) {
    __shared__ int cnt[3];
    int tid = threadIdx.x;
    int i = blockIdx.x * 256 + tid;
    if (tid < 3) cnt[tid] = 0;
    __syncthreads();
    if (i < N) {
        gCnt[i] = 0; gCur[i] = 0;
        atomicAdd(&cnt[ntype[i]], 1);
    }
    if (i < 3) gTypeCur[i] = 0;
    __syncthreads();
    if (tid < 3 && cnt[tid] > 0) atomicAdd(&gTypeCnt[tid], cnt[tid]);
}

__global__ void type_scan() {
    gTypeOff[0] = 0;
    gTypeOff[1] = gTypeCnt[0];
    gTypeOff[2] = gTypeCnt[0] + gTypeCnt[1];
    gTypeCnt[0] = 0; gTypeCnt[1] = 0; gTypeCnt[2] = 0;  // reset for next replay
}

__global__ void type_fill(const int* __restrict__ ntype, int N) {
    __shared__ int cnt[3];
    __shared__ int base[3];
    int tid = threadIdx.x;
    int i = blockIdx.x * 256 + tid;
    if (tid < 3) cnt[tid] = 0;
    __syncthreads();
    int t = 0, p = 0;
    if (i < N) { t = ntype[i]; p = atomicAdd(&cnt[t], 1); }
    __syncthreads();
    if (tid < 3) base[tid] = (cnt[tid] > 0) ? atomicAdd(&gTypeCur[tid], cnt[tid]) : 0;
    __syncthreads();
    if (i < N) gTypeIdx[gTypeOff[t] + base[t] + p] = i;
}

// ---------------------------------------------------------------------------
// QKV + Kt merged: QKV weights in registers (48, reloaded at type change);
// We in SHARED memory (40KB, loaded once per block) -> regs ~85, occ ~2x.
// 16 nodes/block, type-sorted. No K staging round-trip.
// ---------------------------------------------------------------------------
__global__ void qkv_kt_kernel(const float* __restrict__ x,
                              const float* __restrict__ WQ,
                              const float* __restrict__ WK,
                              const float* __restrict__ WV,
                              const float* __restrict__ We, int N) {
    __shared__ float sWe[NET * NH * HD * HD];   // 10240 floats = 40KB
    __shared__ float sx[DIM];
    __shared__ float sk[DIM];
    int tid = threadIdx.x;
    int h = tid >> 4, f = tid & 15;

    for (int i = tid; i < NET * NH * HD * HD; i += 128) sWe[i] = We[i];

    int off1 = gTypeOff[1], off2 = gTypeOff[2];
    float wq[16], wk[16], wv[16];
    int cur_t = -1;
    int m0 = blockIdx.x * NPB;
    __syncthreads();

    for (int i = 0; i < NPB; i++) {
        int m = m0 + i;
        if (m >= N) break;
        int n = gTypeIdx[m];
        int t = (m >= off1) + (m >= off2);
        if (t != cur_t) {
            cur_t = t;
            int base = ((t * NH + h) * HD) * HD + f;
#pragma unroll
            for (int d = 0; d < HD; d++) {
                wq[d] = WQ[base + d * HD];
                wk[d] = WK[base + d * HD];
                wv[d] = WV[base + d * HD];
            }
        }
        sx[tid] = x[n * DIM + tid];
        __syncthreads();
        const float* xr = sx + h * HD;
        float q = 0.f, k = 0.f, v = 0.f;
#pragma unroll
        for (int d = 0; d < HD; d++) {
            float xv = xr[d];
            q = fmaf(xv, wq[d], q);
            k = fmaf(xv, wk[d], k);
            v = fmaf(xv, wv[d], v);
        }
        gQ[n * DIM + tid] = q;
        gVH[n * DIM + tid] = __float2half(v);
        sk[tid] = k;
        __syncthreads();
        const float* kr = sk + h * HD;
#pragma unroll
        for (int et = 0; et < NET; et++) {
            const float* w = sWe + ((et * NH + h) * HD) * HD + f;
            float acc = 0.f;
#pragma unroll
            for (int d = 0; d < HD; d++) acc = fmaf(kr[d], w[d * HD], acc);
            gKtH[(et * NN + n) * DIM + tid] = __float2half(acc);
        }
        __syncthreads();
    }
}

// ---------------------------------------------------------------------------
// CSR build
// ---------------------------------------------------------------------------
__global__ void hist_kernel(const int* __restrict__ ei, int E) {
    int e = blockIdx.x * blockDim.x + threadIdx.x;
    if (e < E) atomicAdd(&gCnt[ei[E + e]], 1);
}

__global__ void scan_local_kernel(int N) {
    __shared__ int sh[1024];
    int t = threadIdx.x;
    int i = blockIdx.x * 1024 + t;
    int v = (i < N) ? gCnt[i] : 0;
    sh[t] = v;
    __syncthreads();
#pragma unroll
    for (int off = 1; off < 1024; off <<= 1) {
        int add = (t >= off) ? sh[t - off] : 0;
        __syncthreads();
        sh[t] += add;
        __syncthreads();
    }
    if (i < N) gRow[i] = sh[t] - v;
    if (t == 1023) gBlkSum[blockIdx.x] = sh[1023];
}

__global__ void scan_block_kernel(int nblk) {
    __shared__ int sh[64];
    int t = threadIdx.x;
    int v = (t < nblk) ? gBlkSum[t] : 0;
    sh[t] = v;
    __syncthreads();
#pragma unroll
    for (int off = 1; off < 64; off <<= 1) {
        int add = (t >= off) ? sh[t - off] : 0;
        __syncthreads();
        sh[t] += add;
        __syncthreads();
    }
    gBlkOff[t] = sh[t] - v;
}

__global__ void scan_add_kernel(int N, int E) {
    int i = blockIdx.x * blockDim.x + threadIdx.x;
    if (i < N) gRow[i] += gBlkOff[i >> 10];
    if (i == 0) gRow[N] = E;
}

__global__ void fill_kernel(const int* __restrict__ ei,
                            const int* __restrict__ etype, int E) {
    int e = blockIdx.x * blockDim.x + threadIdx.x;
    if (e < E) {
        int dst = ei[E + e];
        int p = atomicAdd(&gCur[dst], 1);
        gEid[gRow[dst] + p] = (etype[e] << 20) | ei[e];
    }
}

// ---------------------------------------------------------------------------
// fused attention: warp-per-edge, 4 slots, phase loops 2x unrolled
// ---------------------------------------------------------------------------
__global__ void attn_kernel(const float* __restrict__ mu, int E) {
    int n = blockIdx.x;
    int tid = threadIdx.x;
    int lane = tid & 31;
    int grp = tid >> 5;
    int h = lane >> 2;
    int f4 = lane & 3;
    int d0 = h * HD + 4 * f4;

    __shared__ int s_pk[128];
    __shared__ float s_sc[128][9];
    __shared__ float m_sh[8], den_sh[8], scale_sh[8];
    __shared__ float s_merge[4][DIM];

    float4 q = *(const float4*)&gQ[n * DIM + d0];
    float muh[NET];
#pragma unroll
    for (int et = 0; et < NET; et++) muh[et] = mu[h * NET + et] * 0.25f;

    if (tid < 8) { m_sh[tid] = -3.402823466e38f; den_sh[tid] = 0.f; }
    float4 acc = make_float4(0.f, 0.f, 0.f, 0.f);
    __syncthreads();

    int row0 = gRow[n], row1 = gRow[n + 1];
    for (int cs = row0; cs < row1; cs += 128) {
        int c = min(128, row1 - cs);
        if (tid < c) s_pk[tid] = gEid[cs + tid];
        __syncthreads();

        // ---- phase 1: scores, 2 edges in flight per warp ----
        for (int j = grp; j < c; j += 8) {
            int pkA = s_pk[j];
            int jB = j + 4;
            int hasB = (jB < c);
            int pkB = s_pk[hasB ? jB : j];
            int srcA = pkA & 0xFFFFF, etA = pkA >> 20;
            int srcB = pkB & 0xFFFFF, etB = pkB >> 20;
            uint2 kA = *(const uint2*)&gKtH[(etA * NN + srcA) * DIM + d0];
            uint2 kB = *(const uint2*)&gKtH[(etB * NN + srcB) * DIM + d0];
            float2 a0 = __half22float2(*(__half2*)&kA.x);
            float2 a1 = __half22float2(*(__half2*)&kA.y);
            float sA = q.x * a0.x + q.y * a0.y + q.z * a1.x + q.w * a1.y;
            float2 b0 = __half22float2(*(__half2*)&kB.x);
            float2 b1 = __half22float2(*(__half2*)&kB.y);
            float sB = q.x * b0.x + q.y * b0.y + q.z * b1.x + q.w * b1.y;
            sA += __shfl_xor_sync(0xffffffffu, sA, 1);
            sB += __shfl_xor_sync(0xffffffffu, sB, 1);
            sA += __shfl_xor_sync(0xffffffffu, sA, 2);
            sB += __shfl_xor_sync(0xffffffffu, sB, 2);
            if (f4 == 0) {
                s_sc[j][h] = sA * muh[etA];
                if (hasB) s_sc[jB][h] = sB * muh[etB];
            }
        }
        __syncthreads();

        // ---- phase 2: warp 0 updates per-head stats over the tile ----
        if (grp == 0) {
            float tmax = -3.402823466e38f;
            for (int j = f4; j < c; j += 4) tmax = fmaxf(tmax, s_sc[j][h]);
            tmax = fmaxf(tmax, __shfl_xor_sync(0xffffffffu, tmax, 1));
            tmax = fmaxf(tmax, __shfl_xor_sync(0xffffffffu, tmax, 2));
            float mold = m_sh[h];
            float newm = fmaxf(mold, tmax);
            float dt = 0.f;
            for (int j = f4; j < c; j += 4) {
                float w = __expf(s_sc[j][h] - newm);
                s_sc[j][h] = w;
                dt += w;
            }
            dt += __shfl_xor_sync(0xffffffffu, dt, 1);
            dt += __shfl_xor_sync(0xffffffffu, dt, 2);
            if (f4 == 0) {
                float sc = __expf(mold - newm);
                den_sh[h] = den_sh[h] * sc + dt;
                m_sh[h] = newm;
                scale_sh[h] = sc;
            }
        }
        __syncthreads();

        // ---- phase 3: rescale + weighted V, 2 edges in flight ----
        float sc = scale_sh[h];
        acc.x *= sc; acc.y *= sc; acc.z *= sc; acc.w *= sc;
        for (int j = grp; j < c; j += 8) {
            int jB = j + 4;
            int hasB = (jB < c);
            int srcA = s_pk[j] & 0xFFFFF;
            int srcB = s_pk[hasB ? jB : j] & 0xFFFFF;
            float wA = s_sc[j][h];
            float wB = hasB ? s_sc[jB][h] : 0.f;
            uint2 vA = *(const uint2*)&gVH[srcA * DIM + d0];
            uint2 vB = *(const uint2*)&gVH[srcB * DIM + d0];
            float2 va0 = __half22float2(*(__half2*)&vA.x);
            float2 va1 = __half22float2(*(__half2*)&vA.y);
            acc.x = fmaf(wA, va0.x, acc.x);
            acc.y = fmaf(wA, va0.y, acc.y);
            acc.z = fmaf(wA, va1.x, acc.z);
            acc.w = fmaf(wA, va1.y, acc.w);
            float2 vb0 = __half22float2(*(__half2*)&vB.x);
            float2 vb1 = __half22float2(*(__half2*)&vB.y);
            acc.x = fmaf(wB, vb0.x, acc.x);
            acc.y = fmaf(wB, vb0.y, acc.y);
            acc.z = fmaf(wB, vb1.x, acc.z);
            acc.w = fmaf(wB, vb1.y, acc.w);
        }
        __syncthreads();
    }

    *(float4*)&s_merge[grp][d0] = acc;
    __syncthreads();
    float tot = s_merge[0][tid] + s_merge[1][tid] + s_merge[2][tid] + s_merge[3][tid];
    gAgg[n * DIM + tid] = tot / (den_sh[tid >> 4] + 1e-10f);
}

// ---------------------------------------------------------------------------
// fp16 tensor-core machinery (m16n8k16, f32 accumulate)
// ---------------------------------------------------------------------------
__device__ __forceinline__ unsigned h2pack(float a, float b) {
    __half2 h = __floats2half2_rn(a, b);
    return *(unsigned*)&h;
}
__device__ __forceinline__ void mma_f16(float* c, const unsigned* a, const unsigned* b) {
    asm volatile(
        "mma.sync.aligned.m16n8k16.row.col.f32.f16.f16.f32 "
        "{%0,%1,%2,%3},{%4,%5,%6,%7},{%8,%9},{%0,%1,%2,%3};"
        : "+f"(c[0]), "+f"(c[1]), "+f"(c[2]), "+f"(c[3])
        : "r"(a[0]), "r"(a[1]), "r"(a[2]), "r"(a[3]), "r"(b[0]), "r"(b[1]));
}

#define HMMA_K32(Asp, Bsp, cacc, wy, wx, r, t)                                  \
    _Pragma("unroll")                                                           \
    for (int kk = 0; kk < 2; kk++) {                                            \
        unsigned af[2][4], bf[4][2];                                            \
        _Pragma("unroll")                                                       \
        for (int i = 0; i < 2; i++) {                                           \
            af[i][0] = Asp[wy + i * 16 + r][kk * 8 + t];                        \
            af[i][1] = Asp[wy + i * 16 + r + 8][kk * 8 + t];                    \
            af[i][2] = Asp[wy + i * 16 + r][kk * 8 + t + 4];                    \
            af[i][3] = Asp[wy + i * 16 + r + 8][kk * 8 + t + 4];                \
        }                                                                       \
        _Pragma("unroll")                                                       \
        for (int j = 0; j < 4; j++) {                                           \
            bf[j][0] = Bsp[kk * 8 + t][wx + j * 8 + r];                         \
            bf[j][1] = Bsp[kk * 8 + t + 4][wx + j * 8 + r];                     \
        }                                                                       \
        _Pragma("unroll")                                                       \
        for (int i = 0; i < 2; i++)                                             \
            _Pragma("unroll")                                                   \
            for (int j = 0; j < 4; j++) mma_f16(cacc[i][j], af[i], bf[j]);      \
    }

// ---------------------------------------------------------------------------
// oproj fp16: gHid = LN1(x + gAgg @ Wo + bo); 512 thr, 128-row tiles, K=128
// ---------------------------------------------------------------------------
__global__ void oproj_tc_ln1(const float* __restrict__ x,
                             const float* __restrict__ Wo,
                             const float* __restrict__ bo,
                             const float* __restrict__ g1,
                             const float* __restrict__ bb1, int M) {
    __shared__ unsigned Asp[128][20];
    __shared__ unsigned Bsp[16][132];
    __shared__ float rs[4][128];
    __shared__ float rq[4][128];
    int tid = threadIdx.x, lane = tid & 31, wid = tid >> 5;
    int wy = (wid & 3) * 32, wxg = wid >> 2;
    int wx = wxg * 32;
    int m0 = blockIdx.y * 128;
    int r = lane >> 2, t = lane & 3;
    float c[2][4][4];
#pragma unroll
    for (int i = 0; i < 2; i++)
#pragma unroll
        for (int j = 0; j < 4; j++)
#pragma unroll
            for (int q = 0; q < 4; q++) c[i][j][q] = 0.f;

    for (int k0 = 0; k0 < 128; k0 += 32) {
#pragma unroll
        for (int l = tid; l < 1024; l += 512) {
            int m = l >> 3, kq = (l & 7) << 2;
            int gm = m0 + m; if (gm >= M) gm = M - 1;
            float4 a = *(const float4*)(&gAgg[gm * 128 + k0 + kq]);
            Asp[m][kq >> 1] = h2pack(a.x, a.y);
            Asp[m][(kq >> 1) + 1] = h2pack(a.z, a.w);
        }
        {
            int k2 = tid >> 5, nq = (tid & 31) << 2;
            float4 b0 = *(const float4*)(&Wo[(k0 + 2 * k2) * 128 + nq]);
            float4 b1 = *(const float4*)(&Wo[(k0 + 2 * k2 + 1) * 128 + nq]);
            Bsp[k2][nq]     = h2pack(b0.x, b1.x);
            Bsp[k2][nq + 1] = h2pack(b0.y, b1.y);
            Bsp[k2][nq + 2] = h2pack(b0.z, b1.z);
            Bsp[k2][nq + 3] = h2pack(b0.w, b1.w);
        }
        __syncthreads();
        HMMA_K32(Asp, Bsp, c, wy, wx, r, t);
        __syncthreads();
    }

    float sum[2][2] = {{0.f, 0.f}, {0.f, 0.f}};
    float sq2[2][2] = {{0.f, 0.f}, {0.f, 0.f}};
#pragma unroll
    for (int i = 0; i < 2; i++) {
        int row = m0 + wy + i * 16 + r;
        int rowc  = (row < M) ? row : (M - 1);
        int row2c = (row + 8 < M) ? (row + 8) : (M - 1);
#pragma unroll
        for (int j = 0; j < 4; j++) {
            int col = wx + j * 8 + 2 * t;
            float bc0 = bo[col], bc1 = bo[col + 1];
            float2 h0 = *(const float2*)&x[rowc * 128 + col];
            float2 h1 = *(const float2*)&x[row2c * 128 + col];
            c[i][j][0] += bc0 + h0.x;
            c[i][j][1] += bc1 + h0.y;
            c[i][j][2] += bc0 + h1.x;
            c[i][j][3] += bc1 + h1.y;
            sum[i][0] += c[i][j][0] + c[i][j][1];
            sum[i][1] += c[i][j][2] + c[i][j][3];
            sq2[i][0] = fmaf(c[i][j][0], c[i][j][0], fmaf(c[i][j][1], c[i][j][1], sq2[i][0]));
            sq2[i][1] = fmaf(c[i][j][2], c[i][j][2], fmaf(c[i][j][3], c[i][j][3], sq2[i][1]));
        }
    }
#pragma unroll
    for (int i = 0; i < 2; i++) {
#pragma unroll
        for (int hl = 0; hl < 2; hl++) {
            sum[i][hl] += __shfl_xor_sync(0xffffffffu, sum[i][hl], 1);
            sum[i][hl] += __shfl_xor_sync(0xffffffffu, sum[i][hl], 2);
            sq2[i][hl] += __shfl_xor_sync(0xffffffffu, sq2[i][hl], 1);
            sq2[i][hl] += __shfl_xor_sync(0xffffffffu, sq2[i][hl], 2);
        }
    }
    if (t == 0) {
#pragma unroll
        for (int i = 0; i < 2; i++) {
            rs[wxg][wy + i * 16 + r]     = sum[i][0];
            rs[wxg][wy + i * 16 + r + 8] = sum[i][1];
            rq[wxg][wy + i * 16 + r]     = sq2[i][0];
            rq[wxg][wy + i * 16 + r + 8] = sq2[i][1];
        }
    }
    __syncthreads();
#pragma unroll
    for (int i = 0; i < 2; i++) {
#pragma unroll
        for (int hl = 0; hl < 2; hl++) {
            int rl = wy + i * 16 + r + hl * 8;
            int row = m0 + rl;
            float s  = rs[0][rl] + rs[1][rl] + rs[2][rl] + rs[3][rl];
            float s2 = rq[0][rl] + rq[1][rl] + rq[2][rl] + rq[3][rl];
            float mean = s * (1.f / DIM);
            float var = s2 * (1.f / DIM) - mean * mean;
            float rstd = rsqrtf(var + 1e-5f);
            if (row < M) {
#pragma unroll
                for (int j = 0; j < 4; j++) {
                    int col = wx + j * 8 + 2 * t;
                    float y0 = c[i][j][hl * 2 + 0];
                    float y1 = c[i][j][hl * 2 + 1];
                    float o0 = (y0 - mean) * rstd * g1[col] + bb1[col];
                    float o1 = (y1 - mean) * rstd * g1[col + 1] + bb1[col + 1];
                    *(float2*)&gHid[row * 128 + col] = make_float2(o0, o1);
                }
            }
        }
    }
}

// ---------------------------------------------------------------------------
// FFN1 fp16: gF1[M,512] = gelu(gHid[M,128] @ W1 + b1) -> fp16; 512 thr
// ---------------------------------------------------------------------------
__global__ void ffn1_tc(const float* __restrict__ W1,
                        const float* __restrict__ b1v, int M) {
    __shared__ unsigned Asp[128][20];
    __shared__ unsigned Bsp[16][132];
    int tid = threadIdx.x, lane = tid & 31, wid = tid >> 5;
    int wy = (wid & 3) * 32, wx = (wid >> 2) * 32;
    int m0 = blockIdx.y * 128, n0 = blockIdx.x * 128;
    int r = lane >> 2, t = lane & 3;
    float c[2][4][4];
#pragma unroll
    for (int i = 0; i < 2; i++)
#pragma unroll
        for (int j = 0; j < 4; j++)
#pragma unroll
            for (int q = 0; q < 4; q++) c[i][j][q] = 0.f;

    for (int k0 = 0; k0 < 128; k0 += 32) {
#pragma unroll
        for (int l = tid; l < 1024; l += 512) {
            int m = l >> 3, kq = (l & 7) << 2;
            int gm = m0 + m; if (gm >= M) gm = M - 1;
            float4 a = *(const float4*)(&gHid[gm * 128 + k0 + kq]);
            Asp[m][kq >> 1] = h2pack(a.x, a.y);
            Asp[m][(kq >> 1) + 1] = h2pack(a.z, a.w);
        }
        {
            int k2 = tid >> 5, nq = (tid & 31) << 2;
            float4 b0 = *(const float4*)(&W1[(k0 + 2 * k2) * 512 + n0 + nq]);
            float4 b1 = *(const float4*)(&W1[(k0 + 2 * k2 + 1) * 512 + n0 + nq]);
            Bsp[k2][nq]     = h2pack(b0.x, b1.x);
            Bsp[k2][nq + 1] = h2pack(b0.y, b1.y);
            Bsp[k2][nq + 2] = h2pack(b0.z, b1.z);
            Bsp[k2][nq + 3] = h2pack(b0.w, b1.w);
        }
        __syncthreads();
        HMMA_K32(Asp, Bsp, c, wy, wx, r, t);
        __syncthreads();
    }
#pragma unroll
    for (int i = 0; i < 2; i++) {
        int row = m0 + wy + i * 16 + r;
        int row2 = row + 8;
#pragma unroll
        for (int j = 0; j < 4; j++) {
            int col = n0 + wx + j * 8 + 2 * t;
            float bc0 = b1v[col], bc1 = b1v[col + 1];
            if (row < M) {
                float v0 = c[i][j][0] + bc0;
                float v1 = c[i][j][1] + bc1;
                v0 = 0.5f * v0 * (1.f + erff(v0 * 0.7071067811865476f));
                v1 = 0.5f * v1 * (1.f + erff(v1 * 0.7071067811865476f));
                *(__half2*)&gF1[row * 512 + col] = __floats2half2_rn(v0, v1);
            }
            if (row2 < M) {
                float v0 = c[i][j][2] + bc0;
                float v1 = c[i][j][3] + bc1;
                v0 = 0.5f * v0 * (1.f + erff(v0 * 0.7071067811865476f));
                v1 = 0.5f * v1 * (1.f + erff(v1 * 0.7071067811865476f));
                *(__half2*)&gF1[row2 * 512 + col] = __floats2half2_rn(v0, v1);
            }
        }
    }
}

// ---------------------------------------------------------------------------
// FFN2 fp16: out = LN2(gHid + gF1[M,512] @ W2 + b2); A-feed copies raw half2
// ---------------------------------------------------------------------------
__global__ void ffn2_tc_ln2(const float* __restrict__ W2,
                            const float* __restrict__ b2v,
                            const float* __restrict__ g2,
                            const float* __restrict__ bb2,
                            float* __restrict__ out, int M) {
    __shared__ unsigned Asp[128][20];
    __shared__ unsigned Bsp[16][132];
    __shared__ float rs[4][128];
    __shared__ float rq[4][128];
    int tid = threadIdx.x, lane = tid & 31, wid = tid >> 5;
    int wy = (wid & 3) * 32, wxg = wid >> 2;
    int wx = wxg * 32;
    int m0 = blockIdx.y * 128;
    int r = lane >> 2, t = lane & 3;
    float c[2][4][4];
#pragma unroll
    for (int i = 0; i < 2; i++)
#pragma unroll
        for (int j = 0; j < 4; j++)
#pragma unroll
            for (int q = 0; q < 4; q++) c[i][j][q] = 0.f;

    for (int k0 = 0; k0 < 512; k0 += 32) {
#pragma unroll
        for (int l = tid; l < 1024; l += 512) {
            int m = l >> 3, kq = (l & 7) << 2;
            int gm = m0 + m; if (gm >= M) gm = M - 1;
            uint2 araw = *(const uint2*)(&gF1[gm * 512 + k0 + kq]);
            Asp[m][kq >> 1] = araw.x;
            Asp[m][(kq >> 1) + 1] = araw.y;
        }
        {
            int k2 = tid >> 5, nq = (tid & 31) << 2;
            float4 b0 = *(const float4*)(&W2[(k0 + 2 * k2) * 128 + nq]);
            float4 b1 = *(const float4*)(&W2[(k0 + 2 * k2 + 1) * 128 + nq]);
            Bsp[k2][nq]     = h2pack(b0.x, b1.x);
            Bsp[k2][nq + 1] = h2pack(b0.y, b1.y);
            Bsp[k2][nq + 2] = h2pack(b0.z, b1.z);
            Bsp[k2][nq + 3] = h2pack(b0.w, b1.w);
        }
        __syncthreads();
        HMMA_K32(Asp, Bsp, c, wy, wx, r, t);
        __syncthreads();
    }

    float sum[2][2] = {{0.f, 0.f}, {0.f, 0.f}};
    float sq2[2][2] = {{0.f, 0.f}, {0.f, 0.f}};
#pragma unroll
    for (int i = 0; i < 2; i++) {
        int row = m0 + wy + i * 16 + r;
        int rowc  = (row < M) ? row : (M - 1);
        int row2c = (row + 8 < M) ? (row + 8) : (M - 1);
#pragma unroll
        for (int j = 0; j < 4; j++) {
            int col = wx + j * 8 + 2 * t;
            float bc0 = b2v[col], bc1 = b2v[col + 1];
            float2 h0 = *(const float2*)&gHid[rowc * 128 + col];
            float2 h1 = *(const float2*)&gHid[row2c * 128 + col];
            c[i][j][0] += bc0 + h0.x;
            c[i][j][1] += bc1 + h0.y;
            c[i][j][2] += bc0 + h1.x;
            c[i][j][3] += bc1 + h1.y;
            sum[i][0] += c[i][j][0] + c[i][j][1];
            sum[i][1] += c[i][j][2] + c[i][j][3];
            sq2[i][0] = fmaf(c[i][j][0], c[i][j][0], fmaf(c[i][j][1], c[i][j][1], sq2[i][0]));
            sq2[i][1] = fmaf(c[i][j][2], c[i][j][2], fmaf(c[i][j][3], c[i][j][3], sq2[i][1]));
        }
    }
#pragma unroll
    for (int i = 0; i < 2; i++) {
#pragma unroll
        for (int hl = 0; hl < 2; hl++) {
            sum[i][hl] += __shfl_xor_sync(0xffffffffu, sum[i][hl], 1);
            sum[i][hl] += __shfl_xor_sync(0xffffffffu, sum[i][hl], 2);
            sq2[i][hl] += __shfl_xor_sync(0xffffffffu, sq2[i][hl], 1);
            sq2[i][hl] += __shfl_xor_sync(0xffffffffu, sq2[i][hl], 2);
        }
    }
    if (t == 0) {
#pragma unroll
        for (int i = 0; i < 2; i++) {
            rs[wxg][wy + i * 16 + r]     = sum[i][0];
            rs[wxg][wy + i * 16 + r + 8] = sum[i][1];
            rq[wxg][wy + i * 16 + r]     = sq2[i][0];
            rq[wxg][wy + i * 16 + r + 8] = sq2[i][1];
        }
    }
    __syncthreads();
#pragma unroll
    for (int i = 0; i < 2; i++) {
#pragma unroll
        for (int hl = 0; hl < 2; hl++) {
            int rl = wy + i * 16 + r + hl * 8;
            int row = m0 + rl;
            float s  = rs[0][rl] + rs[1][rl] + rs[2][rl] + rs[3][rl];
            float s2 = rq[0][rl] + rq[1][rl] + rq[2][rl] + rq[3][rl];
            float mean = s * (1.f / DIM);
            float var = s2 * (1.f / DIM) - mean * mean;
            float rstd = rsqrtf(var + 1e-5f);
            if (row < M) {
#pragma unroll
                for (int j = 0; j < 4; j++) {
                    int col = wx + j * 8 + 2 * t;
                    float y0 = c[i][j][hl * 2 + 0];
                    float y1 = c[i][j][hl * 2 + 1];
                    float o0 = (y0 - mean) * rstd * g2[col] + bb2[col];
                    float o1 = (y1 - mean) * rstd * g2[col + 1] + bb2[col + 1];
                    *(float2*)&out[row * 128 + col] = make_float2(o0, o1);
                }
            }
        }
    }
}

// ---------------------------------------------------------------------------
extern "C" void kernel_launch(void* const* d_in, const int* in_sizes, int n_in,
                              void* d_out, int out_size) {
    const float* x     = (const float*)d_in[0];
    const int*   ei    = (const int*)d_in[1];
    const int*   etype = (const int*)d_in[2];
    const int*   ntype = (const int*)d_in[3];
    const float* WQ    = (const float*)d_in[4];
    const float* WK    = (const float*)d_in[5];
    const float* WV    = (const float*)d_in[6];
    const float* We    = (const float*)d_in[7];
    const float* mu    = (const float*)d_in[8];
    const float* Wo    = (const float*)d_in[9];
    const float* bo    = (const float*)d_in[10];
    const float* ln1g  = (const float*)d_in[11];
    const float* ln1b  = (const float*)d_in[12];
    const float* W1    = (const float*)d_in[13];
    const float* b1    = (const float*)d_in[14];
    const float* W2    = (const float*)d_in[15];
    const float* b2    = (const float*)d_in[16];
    const float* ln2g  = (const float*)d_in[17];
    const float* ln2b  = (const float*)d_in[18];

    int N = in_sizes[0] / DIM;   // 50000
    int E = in_sizes[1] / 2;     // 800000
    int nblk = (N + 1023) / 1024;
    int mtiles = (N + 127) / 128;
    int qblks = (N + NPB - 1) / NPB;

    init_hist_kernel<<<(N + 255) / 256, 256>>>(ntype, N);
    type_scan<<<1, 1>>>();
    type_fill<<<(N + 255) / 256, 256>>>(ntype, N);
    qkv_kt_kernel<<<qblks, 128>>>(x, WQ, WK, WV, We, N);
    hist_kernel<<<(E + 255) / 256, 256>>>(ei, E);
    scan_local_kernel<<<nblk, 1024>>>(N);
    scan_block_kernel<<<1, 64>>>(nblk);
    scan_add_kernel<<<(N + 255) / 256, 256>>>(N, E);
    fill_kernel<<<(E + 255) / 256, 256>>>(ei, etype, E);
    attn_kernel<<<N, 128>>>(mu, E);
    oproj_tc_ln1<<<dim3(1, mtiles), 512>>>(x, Wo, bo, ln1g, ln1b, N);
    ffn1_tc<<<dim3(4, mtiles), 512>>>(W1, b1, N);
    ffn2_tc_ln2<<<dim3(1, mtiles), 512>>>(W2, b2, ln2g, ln2b, (float*)d_out, N);
}

// round 17
// speedup vs baseline: 1.1709x; 1.1709x over previous
#include <cuda_runtime.h>
#include <cuda_fp16.h>
#include <math.h>

#define NN 50000
#define NE 800000
#define DIM 128
#define NH 8
#define HD 16
#define NET 5
#define NPB 16   // nodes per block in qkv/kt kernel

// ---- scratch (device globals; no allocation allowed) ----
__device__ float  gQ[NN * DIM];
__device__ __half gKtH[NET * NN * DIM];  // K transformed, fp16 (64MB)
__device__ __half gVH[NN * DIM];         // V, fp16 (12.8MB)
__device__ float  gAgg[NN * DIM];
__device__ float  gHid[NN * DIM];
__device__ __half gF1[NN * 4 * DIM];     // FFN intermediate, fp16 (51MB)
__device__ int    gEid[NE];              // packed: (etype<<20) | src
__device__ int    gCnt[NN];
__device__ int    gCur[NN];
__device__ int    gRow[NN + 1];
__device__ int    gBlkSum[64];
__device__ int    gBlkOff[64];
__device__ int    gTypeIdx[NN];
__device__ int    gTypeCnt[3];
__device__ int    gTypeCur[3];
__device__ int    gTypeOff[3];

// ---------------------------------------------------------------------------
// init + node-type histogram fused (one launch)
// ---------------------------------------------------------------------------
__global__ void init_hist_kernel(const int* __restrict__ ntype, int N) {
    __shared__ int cnt[3];
    int tid = threadIdx.x;
    int i = blockIdx.x * 256 + tid;
    if (tid < 3) cnt[tid] = 0;
    __syncthreads();
    if (i < N) {
        gCnt[i] = 0; gCur[i] = 0;
        atomicAdd(&cnt[ntype[i]], 1);
    }
    if (i < 3) gTypeCur[i] = 0;
    __syncthreads();
    if (tid < 3 && cnt[tid] > 0) atomicAdd(&gTypeCnt[tid], cnt[tid]);
}

__global__ void type_scan() {
    gTypeOff[0] = 0;
    gTypeOff[1] = gTypeCnt[0];
    gTypeOff[2] = gTypeCnt[0] + gTypeCnt[1];
    gTypeCnt[0] = 0; gTypeCnt[1] = 0; gTypeCnt[2] = 0;  // reset for next replay
}

__global__ void type_fill(const int* __restrict__ ntype, int N) {
    __shared__ int cnt[3];
    __shared__ int base[3];
    int tid = threadIdx.x;
    int i = blockIdx.x * 256 + tid;
    if (tid < 3) cnt[tid] = 0;
    __syncthreads();
    int t = 0, p = 0;
    if (i < N) { t = ntype[i]; p = atomicAdd(&cnt[t], 1); }
    __syncthreads();
    if (tid < 3) base[tid] = (cnt[tid] > 0) ? atomicAdd(&gTypeCur[tid], cnt[tid]) : 0;
    __syncthreads();
    if (i < N) gTypeIdx[gTypeOff[t] + base[t] + p] = i;
}

// ---------------------------------------------------------------------------
// helpers
// ---------------------------------------------------------------------------
__device__ __forceinline__ unsigned h2pack(float a, float b) {
    __half2 h = __floats2half2_rn(a, b);
    return *(unsigned*)&h;
}

// ---------------------------------------------------------------------------
// QKV + Kt merged: QKV weights fp32 regs (48, reloaded at type change);
// We packed as 40 half2 REGISTERS; Kt computed via HFMA2 on fp16 K staged in
// smem (8 LDS/node reused over 5 ets). ~120 regs -> 4 blocks/SM.
// ---------------------------------------------------------------------------
__global__ void qkv_kt_kernel(const float* __restrict__ x,
                              const float* __restrict__ WQ,
                              const float* __restrict__ WK,
                              const float* __restrict__ WV,
                              const float* __restrict__ We, int N) {
    __shared__ float  sx[DIM];
    __shared__ __half sk[DIM];
    int tid = threadIdx.x;
    int h = tid >> 4, f = tid & 15;

    // pack We columns into half2 registers: weh[et][d2] = {We[2d2][f], We[2d2+1][f]}
    __half2 weh[NET][8];
#pragma unroll
    for (int et = 0; et < NET; et++) {
        int base = ((et * NH + h) * HD) * HD + f;
#pragma unroll
        for (int d2 = 0; d2 < 8; d2++) {
            unsigned p = h2pack(We[base + (2 * d2) * HD], We[base + (2 * d2 + 1) * HD]);
            weh[et][d2] = *(__half2*)&p;
        }
    }

    int off1 = gTypeOff[1], off2 = gTypeOff[2];
    float wq[16], wk[16], wv[16];
    int cur_t = -1;
    int m0 = blockIdx.x * NPB;

    for (int i = 0; i < NPB; i++) {
        int m = m0 + i;
        if (m >= N) break;
        int n = gTypeIdx[m];
        int t = (m >= off1) + (m >= off2);
        if (t != cur_t) {
            cur_t = t;
            int base = ((t * NH + h) * HD) * HD + f;
#pragma unroll
            for (int d = 0; d < HD; d++) {
                wq[d] = WQ[base + d * HD];
                wk[d] = WK[base + d * HD];
                wv[d] = WV[base + d * HD];
            }
        }
        sx[tid] = x[n * DIM + tid];
        __syncthreads();
        const float* xr = sx + h * HD;
        float q = 0.f, k = 0.f, v = 0.f;
#pragma unroll
        for (int d = 0; d < HD; d++) {
            float xv = xr[d];
            q = fmaf(xv, wq[d], q);
            k = fmaf(xv, wk[d], k);
            v = fmaf(xv, wv[d], v);
        }
        gQ[n * DIM + tid] = q;
        gVH[n * DIM + tid] = __float2half(v);
        sk[tid] = __float2half(k);
        __syncthreads();

        // Kt: 8 broadcast LDS of half2 K, 40 HFMA2, 5 stores
        const __half2* kr2 = (const __half2*)(sk + h * HD);
        __half2 kreg[8];
#pragma unroll
        for (int d2 = 0; d2 < 8; d2++) kreg[d2] = kr2[d2];
#pragma unroll
        for (int et = 0; et < NET; et++) {
            __half2 acc2 = __floats2half2_rn(0.f, 0.f);
#pragma unroll
            for (int d2 = 0; d2 < 8; d2++)
                acc2 = __hfma2(kreg[d2], weh[et][d2], acc2);
            float2 a = __half22float2(acc2);
            gKtH[(et * NN + n) * DIM + tid] = __float2half(a.x + a.y);
        }
        __syncthreads();
    }
}

// ---------------------------------------------------------------------------
// CSR build
// ---------------------------------------------------------------------------
__global__ void hist_kernel(const int* __restrict__ ei, int E) {
    int e = blockIdx.x * blockDim.x + threadIdx.x;
    if (e < E) atomicAdd(&gCnt[ei[E + e]], 1);
}

__global__ void scan_local_kernel(int N) {
    __shared__ int sh[1024];
    int t = threadIdx.x;
    int i = blockIdx.x * 1024 + t;
    int v = (i < N) ? gCnt[i] : 0;
    sh[t] = v;
    __syncthreads();
#pragma unroll
    for (int off = 1; off < 1024; off <<= 1) {
        int add = (t >= off) ? sh[t - off] : 0;
        __syncthreads();
        sh[t] += add;
        __syncthreads();
    }
    if (i < N) gRow[i] = sh[t] - v;
    if (t == 1023) gBlkSum[blockIdx.x] = sh[1023];
}

__global__ void scan_block_kernel(int nblk) {
    __shared__ int sh[64];
    int t = threadIdx.x;
    int v = (t < nblk) ? gBlkSum[t] : 0;
    sh[t] = v;
    __syncthreads();
#pragma unroll
    for (int off = 1; off < 64; off <<= 1) {
        int add = (t >= off) ? sh[t - off] : 0;
        __syncthreads();
        sh[t] += add;
        __syncthreads();
    }
    gBlkOff[t] = sh[t] - v;
}

__global__ void scan_add_kernel(int N, int E) {
    int i = blockIdx.x * blockDim.x + threadIdx.x;
    if (i < N) gRow[i] += gBlkOff[i >> 10];
    if (i == 0) gRow[N] = E;
}

__global__ void fill_kernel(const int* __restrict__ ei,
                            const int* __restrict__ etype, int E) {
    int e = blockIdx.x * blockDim.x + threadIdx.x;
    if (e < E) {
        int dst = ei[E + e];
        int p = atomicAdd(&gCur[dst], 1);
        gEid[gRow[dst] + p] = (etype[e] << 20) | ei[e];
    }
}

// ---------------------------------------------------------------------------
// fused attention: warp-per-edge, 4 slots, phase loops 2x unrolled (R15)
// ---------------------------------------------------------------------------
__global__ void attn_kernel(const float* __restrict__ mu, int E) {
    int n = blockIdx.x;
    int tid = threadIdx.x;
    int lane = tid & 31;
    int grp = tid >> 5;
    int h = lane >> 2;
    int f4 = lane & 3;
    int d0 = h * HD + 4 * f4;

    __shared__ int s_pk[128];
    __shared__ float s_sc[128][9];
    __shared__ float m_sh[8], den_sh[8], scale_sh[8];
    __shared__ float s_merge[4][DIM];

    float4 q = *(const float4*)&gQ[n * DIM + d0];
    float muh[NET];
#pragma unroll
    for (int et = 0; et < NET; et++) muh[et] = mu[h * NET + et] * 0.25f;

    if (tid < 8) { m_sh[tid] = -3.402823466e38f; den_sh[tid] = 0.f; }
    float4 acc = make_float4(0.f, 0.f, 0.f, 0.f);
    __syncthreads();

    int row0 = gRow[n], row1 = gRow[n + 1];
    for (int cs = row0; cs < row1; cs += 128) {
        int c = min(128, row1 - cs);
        if (tid < c) s_pk[tid] = gEid[cs + tid];
        __syncthreads();

        // ---- phase 1: scores, 2 edges in flight per warp ----
        for (int j = grp; j < c; j += 8) {
            int pkA = s_pk[j];
            int jB = j + 4;
            int hasB = (jB < c);
            int pkB = s_pk[hasB ? jB : j];
            int srcA = pkA & 0xFFFFF, etA = pkA >> 20;
            int srcB = pkB & 0xFFFFF, etB = pkB >> 20;
            uint2 kA = *(const uint2*)&gKtH[(etA * NN + srcA) * DIM + d0];
            uint2 kB = *(const uint2*)&gKtH[(etB * NN + srcB) * DIM + d0];
            float2 a0 = __half22float2(*(__half2*)&kA.x);
            float2 a1 = __half22float2(*(__half2*)&kA.y);
            float sA = q.x * a0.x + q.y * a0.y + q.z * a1.x + q.w * a1.y;
            float2 b0 = __half22float2(*(__half2*)&kB.x);
            float2 b1 = __half22float2(*(__half2*)&kB.y);
            float sB = q.x * b0.x + q.y * b0.y + q.z * b1.x + q.w * b1.y;
            sA += __shfl_xor_sync(0xffffffffu, sA, 1);
            sB += __shfl_xor_sync(0xffffffffu, sB, 1);
            sA += __shfl_xor_sync(0xffffffffu, sA, 2);
            sB += __shfl_xor_sync(0xffffffffu, sB, 2);
            if (f4 == 0) {
                s_sc[j][h] = sA * muh[etA];
                if (hasB) s_sc[jB][h] = sB * muh[etB];
            }
        }
        __syncthreads();

        // ---- phase 2: warp 0 updates per-head stats over the tile ----
        if (grp == 0) {
            float tmax = -3.402823466e38f;
            for (int j = f4; j < c; j += 4) tmax = fmaxf(tmax, s_sc[j][h]);
            tmax = fmaxf(tmax, __shfl_xor_sync(0xffffffffu, tmax, 1));
            tmax = fmaxf(tmax, __shfl_xor_sync(0xffffffffu, tmax, 2));
            float mold = m_sh[h];
            float newm = fmaxf(mold, tmax);
            float dt = 0.f;
            for (int j = f4; j < c; j += 4) {
                float w = __expf(s_sc[j][h] - newm);
                s_sc[j][h] = w;
                dt += w;
            }
            dt += __shfl_xor_sync(0xffffffffu, dt, 1);
            dt += __shfl_xor_sync(0xffffffffu, dt, 2);
            if (f4 == 0) {
                float sc = __expf(mold - newm);
                den_sh[h] = den_sh[h] * sc + dt;
                m_sh[h] = newm;
                scale_sh[h] = sc;
            }
        }
        __syncthreads();

        // ---- phase 3: rescale + weighted V, 2 edges in flight ----
        float sc = scale_sh[h];
        acc.x *= sc; acc.y *= sc; acc.z *= sc; acc.w *= sc;
        for (int j = grp; j < c; j += 8) {
            int jB = j + 4;
            int hasB = (jB < c);
            int srcA = s_pk[j] & 0xFFFFF;
            int srcB = s_pk[hasB ? jB : j] & 0xFFFFF;
            float wA = s_sc[j][h];
            float wB = hasB ? s_sc[jB][h] : 0.f;
            uint2 vA = *(const uint2*)&gVH[srcA * DIM + d0];
            uint2 vB = *(const uint2*)&gVH[srcB * DIM + d0];
            float2 va0 = __half22float2(*(__half2*)&vA.x);
            float2 va1 = __half22float2(*(__half2*)&vA.y);
            acc.x = fmaf(wA, va0.x, acc.x);
            acc.y = fmaf(wA, va0.y, acc.y);
            acc.z = fmaf(wA, va1.x, acc.z);
            acc.w = fmaf(wA, va1.y, acc.w);
            float2 vb0 = __half22float2(*(__half2*)&vB.x);
            float2 vb1 = __half22float2(*(__half2*)&vB.y);
            acc.x = fmaf(wB, vb0.x, acc.x);
            acc.y = fmaf(wB, vb0.y, acc.y);
            acc.z = fmaf(wB, vb1.x, acc.z);
            acc.w = fmaf(wB, vb1.y, acc.w);
        }
        __syncthreads();
    }

    *(float4*)&s_merge[grp][d0] = acc;
    __syncthreads();
    float tot = s_merge[0][tid] + s_merge[1][tid] + s_merge[2][tid] + s_merge[3][tid];
    gAgg[n * DIM + tid] = tot / (den_sh[tid >> 4] + 1e-10f);
}

// ---------------------------------------------------------------------------
// fp16 tensor-core machinery (m16n8k16, f32 accumulate)
// ---------------------------------------------------------------------------
__device__ __forceinline__ void mma_f16(float* c, const unsigned* a, const unsigned* b) {
    asm volatile(
        "mma.sync.aligned.m16n8k16.row.col.f32.f16.f16.f32 "
        "{%0,%1,%2,%3},{%4,%5,%6,%7},{%8,%9},{%0,%1,%2,%3};"
        : "+f"(c[0]), "+f"(c[1]), "+f"(c[2]), "+f"(c[3])
        : "r"(a[0]), "r"(a[1]), "r"(a[2]), "r"(a[3]), "r"(b[0]), "r"(b[1]));
}

#define HMMA_K32(Asp, Bsp, cacc, wy, wx, r, t)                                  \
    _Pragma("unroll")                                                           \
    for (int kk = 0; kk < 2; kk++) {                                            \
        unsigned af[2][4], bf[4][2];                                            \
        _Pragma("unroll")                                                       \
        for (int i = 0; i < 2; i++) {                                           \
            af[i][0] = Asp[wy + i * 16 + r][kk * 8 + t];                        \
            af[i][1] = Asp[wy + i * 16 + r + 8][kk * 8 + t];                    \
            af[i][2] = Asp[wy + i * 16 + r][kk * 8 + t + 4];                    \
            af[i][3] = Asp[wy + i * 16 + r + 8][kk * 8 + t + 4];                \
        }                                                                       \
        _Pragma("unroll")                                                       \
        for (int j = 0; j < 4; j++) {                                           \
            bf[j][0] = Bsp[kk * 8 + t][wx + j * 8 + r];                         \
            bf[j][1] = Bsp[kk * 8 + t + 4][wx + j * 8 + r];                     \
        }                                                                       \
        _Pragma("unroll")                                                       \
        for (int i = 0; i < 2; i++)                                             \
            _Pragma("unroll")                                                   \
            for (int j = 0; j < 4; j++) mma_f16(cacc[i][j], af[i], bf[j]);      \
    }

// ---------------------------------------------------------------------------
// oproj fp16: gHid = LN1(x + gAgg @ Wo + bo); 512 thr, 128-row tiles, K=128
// ---------------------------------------------------------------------------
__global__ void oproj_tc_ln1(const float* __restrict__ x,
                             const float* __restrict__ Wo,
                             const float* __restrict__ bo,
                             const float* __restrict__ g1,
                             const float* __restrict__ bb1, int M) {
    __shared__ unsigned Asp[128][20];
    __shared__ unsigned Bsp[16][132];
    __shared__ float rs[4][128];
    __shared__ float rq[4][128];
    int tid = threadIdx.x, lane = tid & 31, wid = tid >> 5;
    int wy = (wid & 3) * 32, wxg = wid >> 2;
    int wx = wxg * 32;
    int m0 = blockIdx.y * 128;
    int r = lane >> 2, t = lane & 3;
    float c[2][4][4];
#pragma unroll
    for (int i = 0; i < 2; i++)
#pragma unroll
        for (int j = 0; j < 4; j++)
#pragma unroll
            for (int q = 0; q < 4; q++) c[i][j][q] = 0.f;

    for (int k0 = 0; k0 < 128; k0 += 32) {
#pragma unroll
        for (int l = tid; l < 1024; l += 512) {
            int m = l >> 3, kq = (l & 7) << 2;
            int gm = m0 + m; if (gm >= M) gm = M - 1;
            float4 a = *(const float4*)(&gAgg[gm * 128 + k0 + kq]);
            Asp[m][kq >> 1] = h2pack(a.x, a.y);
            Asp[m][(kq >> 1) + 1] = h2pack(a.z, a.w);
        }
        {
            int k2 = tid >> 5, nq = (tid & 31) << 2;
            float4 b0 = *(const float4*)(&Wo[(k0 + 2 * k2) * 128 + nq]);
            float4 b1 = *(const float4*)(&Wo[(k0 + 2 * k2 + 1) * 128 + nq]);
            Bsp[k2][nq]     = h2pack(b0.x, b1.x);
            Bsp[k2][nq + 1] = h2pack(b0.y, b1.y);
            Bsp[k2][nq + 2] = h2pack(b0.z, b1.z);
            Bsp[k2][nq + 3] = h2pack(b0.w, b1.w);
        }
        __syncthreads();
        HMMA_K32(Asp, Bsp, c, wy, wx, r, t);
        __syncthreads();
    }

    float sum[2][2] = {{0.f, 0.f}, {0.f, 0.f}};
    float sq2[2][2] = {{0.f, 0.f}, {0.f, 0.f}};
#pragma unroll
    for (int i = 0; i < 2; i++) {
        int row = m0 + wy + i * 16 + r;
        int rowc  = (row < M) ? row : (M - 1);
        int row2c = (row + 8 < M) ? (row + 8) : (M - 1);
#pragma unroll
        for (int j = 0; j < 4; j++) {
            int col = wx + j * 8 + 2 * t;
            float bc0 = bo[col], bc1 = bo[col + 1];
            float2 h0 = *(const float2*)&x[rowc * 128 + col];
            float2 h1 = *(const float2*)&x[row2c * 128 + col];
            c[i][j][0] += bc0 + h0.x;
            c[i][j][1] += bc1 + h0.y;
            c[i][j][2] += bc0 + h1.x;
            c[i][j][3] += bc1 + h1.y;
            sum[i][0] += c[i][j][0] + c[i][j][1];
            sum[i][1] += c[i][j][2] + c[i][j][3];
            sq2[i][0] = fmaf(c[i][j][0], c[i][j][0], fmaf(c[i][j][1], c[i][j][1], sq2[i][0]));
            sq2[i][1] = fmaf(c[i][j][2], c[i][j][2], fmaf(c[i][j][3], c[i][j][3], sq2[i][1]));
        }
    }
#pragma unroll
    for (int i = 0; i < 2; i++) {
#pragma unroll
        for (int hl = 0; hl < 2; hl++) {
            sum[i][hl] += __shfl_xor_sync(0xffffffffu, sum[i][hl], 1);
            sum[i][hl] += __shfl_xor_sync(0xffffffffu, sum[i][hl], 2);
            sq2[i][hl] += __shfl_xor_sync(0xffffffffu, sq2[i][hl], 1);
            sq2[i][hl] += __shfl_xor_sync(0xffffffffu, sq2[i][hl], 2);
        }
    }
    if (t == 0) {
#pragma unroll
        for (int i = 0; i < 2; i++) {
            rs[wxg][wy + i * 16 + r]     = sum[i][0];
            rs[wxg][wy + i * 16 + r + 8] = sum[i][1];
            rq[wxg][wy + i * 16 + r]     = sq2[i][0];
            rq[wxg][wy + i * 16 + r + 8] = sq2[i][1];
        }
    }
    __syncthreads();
#pragma unroll
    for (int i = 0; i < 2; i++) {
#pragma unroll
        for (int hl = 0; hl < 2; hl++) {
            int rl = wy + i * 16 + r + hl * 8;
            int row = m0 + rl;
            float s  = rs[0][rl] + rs[1][rl] + rs[2][rl] + rs[3][rl];
            float s2 = rq[0][rl] + rq[1][rl] + rq[2][rl] + rq[3][rl];
            float mean = s * (1.f / DIM);
            float var = s2 * (1.f / DIM) - mean * mean;
            float rstd = rsqrtf(var + 1e-5f);
            if (row < M) {
#pragma unroll
                for (int j = 0; j < 4; j++) {
                    int col = wx + j * 8 + 2 * t;
                    float y0 = c[i][j][hl * 2 + 0];
                    float y1 = c[i][j][hl * 2 + 1];
                    float o0 = (y0 - mean) * rstd * g1[col] + bb1[col];
                    float o1 = (y1 - mean) * rstd * g1[col + 1] + bb1[col + 1];
                    *(float2*)&gHid[row * 128 + col] = make_float2(o0, o1);
                }
            }
        }
    }
}

// ---------------------------------------------------------------------------
// FFN1 fp16: gF1[M,512] = gelu(gHid[M,128] @ W1 + b1) -> fp16; 512 thr
// ---------------------------------------------------------------------------
__global__ void ffn1_tc(const float* __restrict__ W1,
                        const float* __restrict__ b1v, int M) {
    __shared__ unsigned Asp[128][20];
    __shared__ unsigned Bsp[16][132];
    int tid = threadIdx.x, lane = tid & 31, wid = tid >> 5;
    int wy = (wid & 3) * 32, wx = (wid >> 2) * 32;
    int m0 = blockIdx.y * 128, n0 = blockIdx.x * 128;
    int r = lane >> 2, t = lane & 3;
    float c[2][4][4];
#pragma unroll
    for (int i = 0; i < 2; i++)
#pragma unroll
        for (int j = 0; j < 4; j++)
#pragma unroll
            for (int q = 0; q < 4; q++) c[i][j][q] = 0.f;

    for (int k0 = 0; k0 < 128; k0 += 32) {
#pragma unroll
        for (int l = tid; l < 1024; l += 512) {
            int m = l >> 3, kq = (l & 7) << 2;
            int gm = m0 + m; if (gm >= M) gm = M - 1;
            float4 a = *(const float4*)(&gHid[gm * 128 + k0 + kq]);
            Asp[m][kq >> 1] = h2pack(a.x, a.y);
            Asp[m][(kq >> 1) + 1] = h2pack(a.z, a.w);
        }
        {
            int k2 = tid >> 5, nq = (tid & 31) << 2;
            float4 b0 = *(const float4*)(&W1[(k0 + 2 * k2) * 512 + n0 + nq]);
            float4 b1 = *(const float4*)(&W1[(k0 + 2 * k2 + 1) * 512 + n0 + nq]);
            Bsp[k2][nq]     = h2pack(b0.x, b1.x);
            Bsp[k2][nq + 1] = h2pack(b0.y, b1.y);
            Bsp[k2][nq + 2] = h2pack(b0.z, b1.z);
            Bsp[k2][nq + 3] = h2pack(b0.w, b1.w);
        }
        __syncthreads();
        HMMA_K32(Asp, Bsp, c, wy, wx, r, t);
        __syncthreads();
    }
#pragma unroll
    for (int i = 0; i < 2; i++) {
        int row = m0 + wy + i * 16 + r;
        int row2 = row + 8;
#pragma unroll
        for (int j = 0; j < 4; j++) {
            int col = n0 + wx + j * 8 + 2 * t;
            float bc0 = b1v[col], bc1 = b1v[col + 1];
            if (row < M) {
                float v0 = c[i][j][0] + bc0;
                float v1 = c[i][j][1] + bc1;
                v0 = 0.5f * v0 * (1.f + erff(v0 * 0.7071067811865476f));
                v1 = 0.5f * v1 * (1.f + erff(v1 * 0.7071067811865476f));
                *(__half2*)&gF1[row * 512 + col] = __floats2half2_rn(v0, v1);
            }
            if (row2 < M) {
                float v0 = c[i][j][2] + bc0;
                float v1 = c[i][j][3] + bc1;
                v0 = 0.5f * v0 * (1.f + erff(v0 * 0.7071067811865476f));
                v1 = 0.5f * v1 * (1.f + erff(v1 * 0.7071067811865476f));
                *(__half2*)&gF1[row2 * 512 + col] = __floats2half2_rn(v0, v1);
            }
        }
    }
}

// ---------------------------------------------------------------------------
// FFN2 fp16: out = LN2(gHid + gF1[M,512] @ W2 + b2); A-feed copies raw half2
// ---------------------------------------------------------------------------
__global__ void ffn2_tc_ln2(const float* __restrict__ W2,
                            const float* __restrict__ b2v,
                            const float* __restrict__ g2,
                            const float* __restrict__ bb2,
                            float* __restrict__ out, int M) {
    __shared__ unsigned Asp[128][20];
    __shared__ unsigned Bsp[16][132];
    __shared__ float rs[4][128];
    __shared__ float rq[4][128];
    int tid = threadIdx.x, lane = tid & 31, wid = tid >> 5;
    int wy = (wid & 3) * 32, wxg = wid >> 2;
    int wx = wxg * 32;
    int m0 = blockIdx.y * 128;
    int r = lane >> 2, t = lane & 3;
    float c[2][4][4];
#pragma unroll
    for (int i = 0; i < 2; i++)
#pragma unroll
        for (int j = 0; j < 4; j++)
#pragma unroll
            for (int q = 0; q < 4; q++) c[i][j][q] = 0.f;

    for (int k0 = 0; k0 < 512; k0 += 32) {
#pragma unroll
        for (int l = tid; l < 1024; l += 512) {
            int m = l >> 3, kq = (l & 7) << 2;
            int gm = m0 + m; if (gm >= M) gm = M - 1;
            uint2 araw = *(const uint2*)(&gF1[gm * 512 + k0 + kq]);
            Asp[m][kq >> 1] = araw.x;
            Asp[m][(kq >> 1) + 1] = araw.y;
        }
        {
            int k2 = tid >> 5, nq = (tid & 31) << 2;
            float4 b0 = *(const float4*)(&W2[(k0 + 2 * k2) * 128 + nq]);
            float4 b1 = *(const float4*)(&W2[(k0 + 2 * k2 + 1) * 128 + nq]);
            Bsp[k2][nq]     = h2pack(b0.x, b1.x);
            Bsp[k2][nq + 1] = h2pack(b0.y, b1.y);
            Bsp[k2][nq + 2] = h2pack(b0.z, b1.z);
            Bsp[k2][nq + 3] = h2pack(b0.w, b1.w);
        }
        __syncthreads();
        HMMA_K32(Asp, Bsp, c, wy, wx, r, t);
        __syncthreads();
    }

    float sum[2][2] = {{0.f, 0.f}, {0.f, 0.f}};
    float sq2[2][2] = {{0.f, 0.f}, {0.f, 0.f}};
#pragma unroll
    for (int i = 0; i < 2; i++) {
        int row = m0 + wy + i * 16 + r;
        int rowc  = (row < M) ? row : (M - 1);
        int row2c = (row + 8 < M) ? (row + 8) : (M - 1);
#pragma unroll
        for (int j = 0; j < 4; j++) {
            int col = wx + j * 8 + 2 * t;
            float bc0 = b2v[col], bc1 = b2v[col + 1];
            float2 h0 = *(const float2*)&gHid[rowc * 128 + col];
            float2 h1 = *(const float2*)&gHid[row2c * 128 + col];
            c[i][j][0] += bc0 + h0.x;
            c[i][j][1] += bc1 + h0.y;
            c[i][j][2] += bc0 + h1.x;
            c[i][j][3] += bc1 + h1.y;
            sum[i][0] += c[i][j][0] + c[i][j][1];
            sum[i][1] += c[i][j][2] + c[i][j][3];
            sq2[i][0] = fmaf(c[i][j][0], c[i][j][0], fmaf(c[i][j][1], c[i][j][1], sq2[i][0]));
            sq2[i][1] = fmaf(c[i][j][2], c[i][j][2], fmaf(c[i][j][3], c[i][j][3], sq2[i][1]));
        }
    }
#pragma unroll
    for (int i = 0; i < 2; i++) {
#pragma unroll
        for (int hl = 0; hl < 2; hl++) {
            sum[i][hl] += __shfl_xor_sync(0xffffffffu, sum[i][hl], 1);
            sum[i][hl] += __shfl_xor_sync(0xffffffffu, sum[i][hl], 2);
            sq2[i][hl] += __shfl_xor_sync(0xffffffffu, sq2[i][hl], 1);
            sq2[i][hl] += __shfl_xor_sync(0xffffffffu, sq2[i][hl], 2);
        }
    }
    if (t == 0) {
#pragma unroll
        for (int i = 0; i < 2; i++) {
            rs[wxg][wy + i * 16 + r]     = sum[i][0];
            rs[wxg][wy + i * 16 + r + 8] = sum[i][1];
            rq[wxg][wy + i * 16 + r]     = sq2[i][0];
            rq[wxg][wy + i * 16 + r + 8] = sq2[i][1];
        }
    }
    __syncthreads();
#pragma unroll
    for (int i = 0; i < 2; i++) {
#pragma unroll
        for (int hl = 0; hl < 2; hl++) {
            int rl = wy + i * 16 + r + hl * 8;
            int row = m0 + rl;
            float s  = rs[0][rl] + rs[1][rl] + rs[2][rl] + rs[3][rl];
            float s2 = rq[0][rl] + rq[1][rl] + rq[2][rl] + rq[3][rl];
            float mean = s * (1.f / DIM);
            float var = s2 * (1.f / DIM) - mean * mean;
            float rstd = rsqrtf(var + 1e-5f);
            if (row < M) {
#pragma unroll
                for (int j = 0; j < 4; j++) {
                    int col = wx + j * 8 + 2 * t;
                    float y0 = c[i][j][hl * 2 + 0];
                    float y1 = c[i][j][hl * 2 + 1];
                    float o0 = (y0 - mean) * rstd * g2[col] + bb2[col];
                    float o1 = (y1 - mean) * rstd * g2[col + 1] + bb2[col + 1];
                    *(float2*)&out[row * 128 + col] = make_float2(o0, o1);
                }
            }
        }
    }
}

// ---------------------------------------------------------------------------
extern "C" void kernel_launch(void* const* d_in, const int* in_sizes, int n_in,
                              void* d_out, int out_size) {
    const float* x     = (const float*)d_in[0];
    const int*   ei    = (const int*)d_in[1];
    const int*   etype = (const int*)d_in[2];
    const int*   ntype = (const int*)d_in[3];
    const float* WQ    = (const float*)d_in[4];
    const float* WK    = (const float*)d_in[5];
    const float* WV    = (const float*)d_in[6];
    const float* We    = (const float*)d_in[7];
    const float* mu    = (const float*)d_in[8];
    const float* Wo    = (const float*)d_in[9];
    const float* bo    = (const float*)d_in[10];
    const float* ln1g  = (const float*)d_in[11];
    const float* ln1b  = (const float*)d_in[12];
    const float* W1    = (const float*)d_in[13];
    const float* b1    = (const float*)d_in[14];
    const float* W2    = (const float*)d_in[15];
    const float* b2    = (const float*)d_in[16];
    const float* ln2g  = (const float*)d_in[17];
    const float* ln2b  = (const float*)d_in[18];

    int N = in_sizes[0] / DIM;   // 50000
    int E = in_sizes[1] / 2;     // 800000
    int nblk = (N + 1023) / 1024;
    int mtiles = (N + 127) / 128;
    int qblks = (N + NPB - 1) / NPB;

    init_hist_kernel<<<(N + 255) / 256, 256>>>(ntype, N);
    type_scan<<<1, 1>>>();
    type_fill<<<(N + 255) / 256, 256>>>(ntype, N);
    qkv_kt_kernel<<<qblks, 128>>>(x, WQ, WK, WV, We, N);
    hist_kernel<<<(E + 255) / 256, 256>>>(ei, E);
    scan_local_kernel<<<nblk, 1024>>>(N);
    scan_block_kernel<<<1, 64>>>(nblk);
    scan_add_kernel<<<(N + 255) / 256, 256>>>(N, E);
    fill_kernel<<<(E + 255) / 256, 256>>>(ei, etype, E);
    attn_kernel<<<N, 128>>>(mu, E);
    oproj_tc_ln1<<<dim3(1, mtiles), 512>>>(x, Wo, bo, ln1g, ln1b, N);
    ffn1_tc<<<dim3(4, mtiles), 512>>>(W1, b1, N);
    ffn2_tc_ln2<<<dim3(1, mtiles), 512>>>(W2, b2, ln2g, ln2b, (float*)d_out, N);
}